// round 3
// baseline (speedup 1.0000x reference)
#include <cuda_runtime.h>
#include <math.h>

#define VOCAB   100000
#define EMBED   64
#define SENT    20
#define MEM     50
#define BATCH   32
#define HOPS    3

// Scratch: 4 context tensors [B,M,E] (mA, mC0, mC1, mC2) + final u [B,E]
__device__ float g_m[4][BATCH * MEM * EMBED];   // 1.6 MB
__device__ float g_u[BATCH * EMBED];

// ---------------------------------------------------------------------------
// f32x2 helpers (Blackwell packed fp32 pipe — 2x FFMA throughput)
// ---------------------------------------------------------------------------
__device__ __forceinline__ void fma2(unsigned long long& acc,
                                     unsigned long long a,
                                     unsigned long long b) {
    asm("fma.rn.f32x2 %0, %1, %2, %0;" : "+l"(acc) : "l"(a), "l"(b));
}
__device__ __forceinline__ unsigned long long pack2(float x, float y) {
    unsigned long long r;
    asm("mov.b64 %0, {%1, %2};" : "=l"(r) : "f"(x), "f"(y));
    return r;
}
__device__ __forceinline__ float2 unpack2(unsigned long long v) {
    float2 r;
    asm("mov.b64 {%0, %1}, %2;" : "=f"(r.x), "=f"(r.y) : "l"(v));
    return r;
}

// ---------------------------------------------------------------------------
// Kernel A: gather + position-encode the 4 context tensors.
// One block per (b, m) pair (1600 blocks), one thread per embed dim.
// ---------------------------------------------------------------------------
__global__ void context_kernel(const int* __restrict__ stories,
                               const float* __restrict__ A,
                               const float* __restrict__ C,
                               const float* __restrict__ enc) {
    int bm = blockIdx.x;           // 0..1599
    int e  = threadIdx.x;          // 0..63

    const int* st = stories + bm * SENT;
    int idxs[SENT];
#pragma unroll
    for (int s = 0; s < SENT; s++) idxs[s] = st[s];

    float a0 = 0.f, a1 = 0.f, a2 = 0.f, a3 = 0.f;
#pragma unroll
    for (int s = 0; s < SENT; s++) {
        float ev = enc[s * EMBED + e];
        size_t off = (size_t)idxs[s] * EMBED + e;
        a0 = fmaf(A[off], ev, a0);
        a1 = fmaf(C[off], ev, a1);
        a2 = fmaf(C[(size_t)VOCAB * EMBED + off], ev, a2);
        a3 = fmaf(C[(size_t)2 * VOCAB * EMBED + off], ev, a3);
    }
    int o = bm * EMBED + e;
    g_m[0][o] = a0;   // mA   (m at hop 0)
    g_m[1][o] = a1;   // mC0  (c at hop 0 == m at hop 1)
    g_m[2][o] = a2;   // mC1  (c at hop 1 == m at hop 2)
    g_m[3][o] = a3;   // mC2  (c at hop 2)
}

// ---------------------------------------------------------------------------
// Kernel B: query embedding + 3-hop attention recursion. One block per batch.
// ---------------------------------------------------------------------------
__global__ void hops_kernel(const int* __restrict__ queries,
                            const float* __restrict__ A,
                            const float* __restrict__ enc) {
    int b   = blockIdx.x;
    int tid = threadIdx.x;         // 0..63

    __shared__ float s_u[EMBED];
    __shared__ float s_p[MEM];
    __shared__ float s_inv;

    // u0 = sum_s A[q[s]] * enc[s]
    float ue = 0.f;
#pragma unroll
    for (int s = 0; s < SENT; s++) {
        int idx = queries[b * SENT + s];
        ue = fmaf(A[(size_t)idx * EMBED + tid], enc[s * EMBED + tid], ue);
    }
    s_u[tid] = ue;
    __syncthreads();

    for (int hop = 0; hop < HOPS; hop++) {
        const float* mX = g_m[hop]     + b * MEM * EMBED;
        const float* cX = g_m[hop + 1] + b * MEM * EMBED;

        // dotted[m] = m[m,:] . u
        if (tid < MEM) {
            float d = 0.f;
#pragma unroll 16
            for (int e = 0; e < EMBED; e++)
                d = fmaf(mX[tid * EMBED + e], s_u[e], d);
            s_p[tid] = d;
        }
        __syncthreads();

        // softmax over 50 elements (tiny — serial in thread 0 is fine)
        if (tid == 0) {
            float mx = -1e30f;
            for (int m = 0; m < MEM; m++) mx = fmaxf(mx, s_p[m]);
            float sum = 0.f;
            for (int m = 0; m < MEM; m++) {
                float p = __expf(s_p[m] - mx);
                s_p[m] = p;
                sum += p;
            }
            s_inv = 1.f / sum;
        }
        __syncthreads();

        // o[e] = sum_m probs[m] * c[m,e];  u += o
        float inv = s_inv;
        float o = 0.f;
#pragma unroll 10
        for (int m = 0; m < MEM; m++)
            o = fmaf(s_p[m] * inv, cX[m * EMBED + tid], o);
        float nu = s_u[tid] + o;
        __syncthreads();
        s_u[tid] = nu;
        __syncthreads();
    }
    g_u[b * EMBED + tid] = s_u[tid];
}

// ---------------------------------------------------------------------------
// Kernel C: out[32, V] = u[32,64] @ C2[V,64]^T
// 128 threads/block, each thread owns 2 vocab rows x all 32 batches.
// Batches packed in pairs -> fma.rn.f32x2 (2x fp32 FMA throughput).
// u transposed+packed in smem: s_up[e][i] = (u[2i][e], u[2i+1][e]).
// ---------------------------------------------------------------------------
__global__ void __launch_bounds__(128) out_gemm(const float* __restrict__ C2,
                                                float* __restrict__ out) {
    __shared__ float s_up[EMBED * 32];   // 8 KB: [e][2i..2i+1] pairs

    int tid = threadIdx.x;
    for (int idx = tid; idx < EMBED * 16; idx += 128) {
        int e = idx >> 4, i = idx & 15;
        s_up[e * 32 + 2 * i]     = g_u[(2 * i)     * EMBED + e];
        s_up[e * 32 + 2 * i + 1] = g_u[(2 * i + 1) * EMBED + e];
    }
    __syncthreads();

    int v0 = blockIdx.x * 256 + tid * 2;
    if (v0 >= VOCAB) return;   // no syncs below — safe early-exit

    unsigned long long acc0[16], acc1[16];
#pragma unroll
    for (int i = 0; i < 16; i++) { acc0[i] = 0ull; acc1[i] = 0ull; }

    const float4* row0 = (const float4*)(C2 + (size_t)v0 * EMBED);
    const float4* row1 = row0 + (EMBED / 4);

#pragma unroll
    for (int ch = 0; ch < 4; ch++) {
        float4 r0[4], r1[4];
#pragma unroll
        for (int j = 0; j < 4; j++) { r0[j] = row0[ch * 4 + j]; r1[j] = row1[ch * 4 + j]; }
        const float* f0 = (const float*)r0;
        const float* f1 = (const float*)r1;
#pragma unroll
        for (int e16 = 0; e16 < 16; e16++) {
            int e = ch * 16 + e16;
            unsigned long long bc0 = pack2(f0[e16], f0[e16]);
            unsigned long long bc1 = pack2(f1[e16], f1[e16]);
            const float4* up4 = (const float4*)(s_up + e * 32);
#pragma unroll
            for (int j = 0; j < 8; j++) {
                float4 q = up4[j];                 // pairs i=2j and i=2j+1
                unsigned long long ua, ub;
                asm("mov.b64 %0, {%1, %2};" : "=l"(ua) : "f"(q.x), "f"(q.y));
                asm("mov.b64 %0, {%1, %2};" : "=l"(ub) : "f"(q.z), "f"(q.w));
                fma2(acc0[2 * j],     ua, bc0);
                fma2(acc1[2 * j],     ua, bc1);
                fma2(acc0[2 * j + 1], ub, bc0);
                fma2(acc1[2 * j + 1], ub, bc1);
            }
        }
    }

#pragma unroll
    for (int i = 0; i < 16; i++) {
        float2 a0 = unpack2(acc0[i]);   // (b=2i @ v0, b=2i+1 @ v0)
        float2 a1 = unpack2(acc1[i]);   // (b=2i @ v1, b=2i+1 @ v1)
        *(float2*)(out + (size_t)(2 * i)     * VOCAB + v0) = make_float2(a0.x, a1.x);
        *(float2*)(out + (size_t)(2 * i + 1) * VOCAB + v0) = make_float2(a0.y, a1.y);
    }
}

// ---------------------------------------------------------------------------
extern "C" void kernel_launch(void* const* d_in, const int* in_sizes, int n_in,
                              void* d_out, int out_size) {
    const int*   stories = (const int*)d_in[0];
    const int*   queries = (const int*)d_in[1];
    const float* A       = (const float*)d_in[2];
    const float* C       = (const float*)d_in[3];
    const float* enc     = (const float*)d_in[4];
    float*       out     = (float*)d_out;

    context_kernel<<<BATCH * MEM, EMBED>>>(stories, A, C, enc);
    hops_kernel<<<BATCH, EMBED>>>(queries, A, enc);
    out_gemm<<<(VOCAB + 255) / 256, 128>>>(C + (size_t)2 * VOCAB * EMBED, out);
}